// round 15
// baseline (speedup 1.0000x reference)
#include <cuda_runtime.h>
#include <cuda_fp16.h>
#include <mma.h>
#include <math.h>
#include <stdint.h>

using namespace nvcuda;

// Problem constants
#define BATCH 2
#define SEQ 2048
#define DIM 768
#define NHEAD 12
#define HDIM 64
#define QKV_DIM (3 * DIM)     // 2304
#define M_TOTAL (BATCH * SEQ) // 4096
#define SCALE 0.125f          // 64^-0.5

// Scratch (device globals; no allocations allowed)
__device__ __half g_q[BATCH * NHEAD * SEQ * HDIM];
__device__ __half g_k[BATCH * NHEAD * SEQ * HDIM];
__device__ __half g_v[BATCH * NHEAD * SEQ * HDIM];
__device__ __half g_kc[BATCH * NHEAD * SEQ * HDIM];  // gathered+padded K
__device__ __half g_vc[BATCH * NHEAD * SEQ * HDIM];  // gathered+padded V
__device__ __half g_x[M_TOTAL * DIM];
__device__ __half g_a[M_TOTAL * DIM];     // fp16-rounded inputs
__device__ __half g_wq[QKV_DIM * DIM];    // fp16-rounded w_qkv
__device__ __half g_wf[DIM * DIM];        // fp16-rounded w_fc
__device__ int    g_idx[BATCH * SEQ];
__device__ int    g_cnt[BATCH];

typedef wmma::fragment<wmma::matrix_a, 16, 16, 16, __half, wmma::row_major> HA;
typedef wmma::fragment<wmma::matrix_b, 16, 16, 16, __half, wmma::col_major> HBc;
typedef wmma::fragment<wmma::accumulator, 16, 16, 16, float> HC;

__device__ __forceinline__ uint32_t smem_u32(const void* p) {
    uint32_t a;
    asm("{ .reg .u64 t; cvta.to.shared.u64 t, %1; cvt.u32.u64 %0, t; }" : "=r"(a) : "l"(p));
    return a;
}
__device__ __forceinline__ void ldsm_x4(uint32_t& r0, uint32_t& r1, uint32_t& r2,
                                        uint32_t& r3, uint32_t addr) {
    asm volatile("ldmatrix.sync.aligned.m8n8.x4.shared.b16 {%0,%1,%2,%3}, [%4];"
                 : "=r"(r0), "=r"(r1), "=r"(r2), "=r"(r3) : "r"(addr));
}
__device__ __forceinline__ void ldsm_x4_t(uint32_t& r0, uint32_t& r1, uint32_t& r2,
                                          uint32_t& r3, uint32_t addr) {
    asm volatile("ldmatrix.sync.aligned.m8n8.x4.trans.shared.b16 {%0,%1,%2,%3}, [%4];"
                 : "=r"(r0), "=r"(r1), "=r"(r2), "=r"(r3) : "r"(addr));
}
__device__ __forceinline__ void mma16816(float* c, uint32_t a0, uint32_t a1,
                                         uint32_t a2, uint32_t a3,
                                         uint32_t b0, uint32_t b1) {
    asm volatile(
        "mma.sync.aligned.m16n8k16.row.col.f32.f16.f16.f32 "
        "{%0,%1,%2,%3},{%4,%5,%6,%7},{%8,%9},{%0,%1,%2,%3};"
        : "+f"(c[0]), "+f"(c[1]), "+f"(c[2]), "+f"(c[3])
        : "r"(a0), "r"(a1), "r"(a2), "r"(a3), "r"(b0), "r"(b1));
}
__device__ __forceinline__ uint32_t packh2(float a, float b) {
    __half2 h = __floats2half2_rn(a, b);
    return *(uint32_t*)&h;
}

// ---------------------------------------------------------------------------
// Kernel -1: fused fp32 -> fp16 round-to-nearest for all three tensors.
// ---------------------------------------------------------------------------
#define N8_A (M_TOTAL * DIM / 8)
#define N8_WQ (QKV_DIM * DIM / 8)
#define N8_WF (DIM * DIM / 8)
#define N8_TOTAL (N8_A + N8_WQ + N8_WF)

__global__ void convert_all_kernel(const float* __restrict__ a,
                                   const float* __restrict__ wq,
                                   const float* __restrict__ wf)
{
    int i = blockIdx.x * blockDim.x + threadIdx.x;
    if (i >= N8_TOTAL) return;
    const float* src;
    __half* dst;
    int j;
    if (i < N8_A) {
        src = a; dst = g_a; j = i;
    } else if (i < N8_A + N8_WQ) {
        src = wq; dst = g_wq; j = i - N8_A;
    } else {
        src = wf; dst = g_wf; j = i - N8_A - N8_WQ;
    }
    float4 x = *(const float4*)&src[j * 8];
    float4 y = *(const float4*)&src[j * 8 + 4];
    __half2 h0 = __floats2half2_rn(x.x, x.y);
    __half2 h1 = __floats2half2_rn(x.z, x.w);
    __half2 h2 = __floats2half2_rn(y.x, y.y);
    __half2 h3 = __floats2half2_rn(y.z, y.w);
    uint4 u;
    u.x = *(uint32_t*)&h0; u.y = *(uint32_t*)&h1;
    u.z = *(uint32_t*)&h2; u.w = *(uint32_t*)&h3;
    *(uint4*)&dst[j * 8] = u;
}

// ---------------------------------------------------------------------------
// Kernel 0: per-batch compaction of unmasked key indices (mask <= 0).
// ---------------------------------------------------------------------------
__global__ void compact_kernel(const int* __restrict__ mask)
{
    __shared__ int cnts[256];
    const int b = blockIdx.x;
    const int t = threadIdx.x;
    const int PER = SEQ / 256; // 8

    int m[PER];
    int local = 0;
#pragma unroll
    for (int i = 0; i < PER; i++) {
        m[i] = mask[b * SEQ + t * PER + i];
        local += (m[i] <= 0);
    }
    cnts[t] = local;
    __syncthreads();
    for (int off = 1; off < 256; off <<= 1) {
        int v = (t >= off) ? cnts[t - off] : 0;
        __syncthreads();
        cnts[t] += v;
        __syncthreads();
    }
    int w = cnts[t] - local;
#pragma unroll
    for (int i = 0; i < PER; i++)
        if (m[i] <= 0) g_idx[b * SEQ + (w++)] = t * PER + i;
    if (t == 255) g_cnt[b] = cnts[255];
}

// ---------------------------------------------------------------------------
// Kernel 0b: gather compacted K/V rows into contiguous zero-padded buffers.
// g_kc[bh][i][64] = K[bh][idx[i]][:] for i < cnt, zeros for i in [cnt, cnt64).
// Grid (SEQ/128, BATCH*NHEAD), 256 threads; block handles 128 rows of one bh.
// ---------------------------------------------------------------------------
__global__ void gather_kv_kernel()
{
    const int bh = blockIdx.y;
    const int b = bh / NHEAD;
    const int cnt = g_cnt[b];
    const int cnt64 = (cnt + 63) & ~63;
    const int r0 = blockIdx.x << 7;
    if (r0 >= cnt64) return;

    const int tid = threadIdx.x;
    const __half* kb = g_k + (size_t)bh * SEQ * HDIM;
    const __half* vb = g_v + (size_t)bh * SEQ * HDIM;
    __half* kc = g_kc + (size_t)bh * SEQ * HDIM;
    __half* vc = g_vc + (size_t)bh * SEQ * HDIM;
    const int* idxb = g_idx + b * SEQ;

#pragma unroll
    for (int i = 0; i < 4; i++) {
        int idx = tid + 256 * i;          // 0..1023 chunks (128 rows x 8)
        int r = r0 + (idx >> 3);
        int c8 = (idx & 7) << 3;
        if (r >= cnt64) break;
        uint4 kv, vv;
        if (r < cnt) {
            int s = idxb[r];
            kv = *(const uint4*)&kb[(size_t)s * HDIM + c8];
            vv = *(const uint4*)&vb[(size_t)s * HDIM + c8];
        } else {
            kv = make_uint4(0, 0, 0, 0);
            vv = make_uint4(0, 0, 0, 0);
        }
        *(uint4*)&kc[(size_t)r * HDIM + c8] = kv;
        *(uint4*)&vc[(size_t)r * HDIM + c8] = vv;
    }
}

// ---------------------------------------------------------------------------
// fp16 GEMM config.
// ---------------------------------------------------------------------------
#define BK 32
#define LDH 40
#define NCHUNK (DIM / BK)  // 24

__global__ __launch_bounds__(128) void qkv_kernel()
{
    __shared__ __half As[128 * LDH];
    __shared__ __half Ws[128 * LDH];

    const int tid = threadIdx.x;
    const int warp = tid >> 5;
    const int lane = tid & 31;
    const int wy = warp >> 1;
    const int wx = warp & 1;
    const int m0 = blockIdx.y << 7;
    const int d0 = blockIdx.x << 7;

    HC acc[4][4];
#pragma unroll
    for (int i = 0; i < 4; i++)
#pragma unroll
        for (int j = 0; j < 4; j++) wmma::fill_fragment(acc[i][j], 0.f);

    const int ar = tid >> 2;
    const int ac8 = (tid & 3) << 3;

    uint4 pa[4], pw[4];
#pragma unroll
    for (int i = 0; i < 4; i++) {
        pa[i] = *(const uint4*)&g_a[(size_t)(m0 + ar + 32 * i) * DIM + ac8];
        pw[i] = *(const uint4*)&g_wq[(size_t)(d0 + ar + 32 * i) * DIM + ac8];
    }

    for (int c = 0; c < NCHUNK; c++) {
#pragma unroll
        for (int i = 0; i < 4; i++) {
            *(uint4*)&As[(ar + 32 * i) * LDH + ac8] = pa[i];
            *(uint4*)&Ws[(ar + 32 * i) * LDH + ac8] = pw[i];
        }
        __syncthreads();
        if (c + 1 < NCHUNK) {
            const int kc = (c + 1) * BK;
#pragma unroll
            for (int i = 0; i < 4; i++) {
                pa[i] = *(const uint4*)&g_a[(size_t)(m0 + ar + 32 * i) * DIM + kc + ac8];
                pw[i] = *(const uint4*)&g_wq[(size_t)(d0 + ar + 32 * i) * DIM + kc + ac8];
            }
        }
#pragma unroll
        for (int ks = 0; ks < 2; ks++) {
            HA am[4];
            HBc bn[4];
#pragma unroll
            for (int ms = 0; ms < 4; ms++)
                wmma::load_matrix_sync(am[ms], &As[(wy * 64 + ms * 16) * LDH + ks * 16], LDH);
#pragma unroll
            for (int ns = 0; ns < 4; ns++)
                wmma::load_matrix_sync(bn[ns], &Ws[(wx * 64 + ns * 16) * LDH + ks * 16], LDH);
#pragma unroll
            for (int ms = 0; ms < 4; ms++)
#pragma unroll
                for (int ns = 0; ns < 4; ns++)
                    wmma::mma_sync(acc[ms][ns], am[ms], bn[ns], acc[ms][ns]);
        }
        __syncthreads();
    }

    float* Ep = (float*)As + warp * (16 * 20);
    const int bIdx = m0 >> 11;
    const int n0 = (m0 & 2047) + wy * 64;
    const int dg = d0 + wx * 64;
    const int which = dg / DIM;
    const int dbase = dg % DIM;
    __half* dstb = (which == 0) ? g_q : (which == 1) ? g_k : g_v;
    const size_t headbase0 = ((size_t)bIdx * NHEAD) * SEQ;
    const int row = lane >> 1, c0 = (lane & 1) << 3;

#pragma unroll
    for (int ms = 0; ms < 4; ms++)
#pragma unroll
        for (int ns = 0; ns < 4; ns++) {
            wmma::store_matrix_sync(Ep, acc[ms][ns], 20, wmma::mem_row_major);
            __syncwarp();
            const float* src = &Ep[row * 20 + c0];
            __half tmp[8];
#pragma unroll
            for (int j = 0; j < 8; j++) tmp[j] = __float2half_rn(src[j]);
            int dl = dbase + ns * 16;
            int h = dl >> 6;
            int hd = (dl & 63) + c0;
            size_t off = (headbase0 + (size_t)h * SEQ + n0 + ms * 16 + row) * HDIM + hd;
            *(uint4*)&dstb[off] = *(uint4*)tmp;
            __syncwarp();
        }
}

// ---------------------------------------------------------------------------
// Kernel 2: flash attention, raw mma.m16n8k16, in-register softmax, over
// PRE-GATHERED contiguous K/V (g_kc/g_vc). Sequential loads, no index math;
// exp mask only on the final (partial) tile.
// ---------------------------------------------------------------------------
#define AQS 72  // smem stride (halves) for Q/K/V tiles

__global__ __launch_bounds__(256, 2) void attn_kernel()
{
    __shared__ __half Qs[128 * AQS];   // 18432 B
    __shared__ __half Ks[64 * AQS];    //  9216 B
    __shared__ __half Vs[64 * AQS];    //  9216 B
    __shared__ float meanv[64];

    const int tid = threadIdx.x;
    const int warp = tid >> 5;
    const int lane = tid & 31;
    const int g = lane >> 2;
    const int q = lane & 3;
    const int bh = blockIdx.y;
    const int b = bh / NHEAD, h = bh % NHEAD;
    const int q0 = blockIdx.x * 128;
    const __half* qb = g_q + (size_t)bh * SEQ * HDIM;
    const __half* kcb = g_kc + (size_t)bh * SEQ * HDIM;
    const __half* vcb = g_vc + (size_t)bh * SEQ * HDIM;
    const int cnt = g_cnt[b];

    if (cnt == 0) {
        // All keys masked: softmax uniform -> output = mean of V rows.
        const __half* vb = g_v + (size_t)bh * SEQ * HDIM;
        if (tid < 64) {
            float acc = 0.f;
            for (int k = 0; k < SEQ; k++) acc += __half2float(vb[(size_t)k * HDIM + tid]);
            meanv[tid] = acc / (float)SEQ;
        }
        __syncthreads();
        int row = tid >> 1, half32 = (tid & 1) * 32;
        __half* dst = g_x + (size_t)(b * SEQ + q0 + row) * DIM + h * HDIM + half32;
#pragma unroll
        for (int c = 0; c < 32; c++) dst[c] = __float2half_rn(meanv[half32 + c]);
        return;
    }

    // Load Q tile (128 x 64 halves) into Qs
#pragma unroll
    for (int i = 0; i < 4; i++) {
        int idx = tid + 256 * i;
        int r = idx >> 3, c8 = (idx & 7) << 3;
        *(uint4*)&Qs[r * AQS + c8] = *(const uint4*)&qb[(size_t)(q0 + r) * HDIM + c8];
    }
    __syncthreads();

    const int lm = lane >> 3, lr8 = lane & 7;

    // Q A-frags preloaded, reused all tiles.
    uint32_t aq[4][4];
    {
        uint32_t qaddr = smem_u32(&Qs[(warp * 16 + (lm & 1) * 8 + lr8) * AQS + (lm >> 1) * 8]);
#pragma unroll
        for (int ks = 0; ks < 4; ks++)
            ldsm_x4(aq[ks][0], aq[ks][1], aq[ks][2], aq[ks][3], qaddr + ks * 32);
    }

    const uint32_t kaddr0 = smem_u32(&Ks[((lm >> 1) * 8 + lr8) * AQS + (lm & 1) * 8]);
    const uint32_t vaddr0 = smem_u32(&Vs[((lm & 1) * 8 + lr8) * AQS + (lm >> 1) * 8]);

    float oacc[8][4];
#pragma unroll
    for (int dn = 0; dn < 8; dn++)
#pragma unroll
        for (int e = 0; e < 4; e++) oacc[dn][e] = 0.f;
    float rs_lo = 0.f, rs_hi = 0.f;

    const int ntiles = (cnt + 63) >> 6;

    // Thread's fixed load slot in the 64x64 tile
    const int lrr = tid >> 3;            // row 0..31 (+32 for i=1)
    const int lc8 = (tid & 7) << 3;      // col

    // Prologue: tile 0 into registers (sequential, unguarded - pad is zeroed)
    uint4 kreg[2], vreg[2];
#pragma unroll
    for (int i = 0; i < 2; i++) {
        kreg[i] = *(const uint4*)&kcb[(size_t)(lrr + 32 * i) * HDIM + lc8];
        vreg[i] = *(const uint4*)&vcb[(size_t)(lrr + 32 * i) * HDIM + lc8];
    }

    for (int tile = 0; tile < ntiles; tile++) {
        const int k0 = tile << 6;
        __syncthreads(); // prev-tile ldmatrix reads of Ks/Vs done

#pragma unroll
        for (int i = 0; i < 2; i++) {
            *(uint4*)&Ks[(lrr + 32 * i) * AQS + lc8] = kreg[i];
            *(uint4*)&Vs[(lrr + 32 * i) * AQS + lc8] = vreg[i];
        }
        __syncthreads(); // K/V visible

        // Prefetch next tile (sequential, unguarded)
        if (tile + 1 < ntiles) {
            const int kn = k0 + 64;
#pragma unroll
            for (int i = 0; i < 2; i++) {
                kreg[i] = *(const uint4*)&kcb[(size_t)(kn + lrr + 32 * i) * HDIM + lc8];
                vreg[i] = *(const uint4*)&vcb[(size_t)(kn + lrr + 32 * i) * HDIM + lc8];
            }
        }

        // ---- S = Q K^T (16 x 64 per warp) in registers ----
        float sacc[8][4];
#pragma unroll
        for (int jn = 0; jn < 8; jn++)
#pragma unroll
            for (int e = 0; e < 4; e++) sacc[jn][e] = 0.f;

#pragma unroll
        for (int ks = 0; ks < 4; ks++) {
#pragma unroll
            for (int jnp = 0; jnp < 4; jnp++) {
                uint32_t b0, b1, b2, b3;
                ldsm_x4(b0, b1, b2, b3, kaddr0 + jnp * (16 * AQS * 2) + ks * 32);
                mma16816(sacc[2 * jnp],     aq[ks][0], aq[ks][1], aq[ks][2], aq[ks][3], b0, b1);
                mma16816(sacc[2 * jnp + 1], aq[ks][0], aq[ks][1], aq[ks][2], aq[ks][3], b2, b3);
            }
        }

        // ---- exp in-register; mask only on the final partial tile ----
        uint32_t eh[8][2];
        if (k0 + 64 <= cnt) {
#pragma unroll
            for (int jn = 0; jn < 8; jn++) {
                float e0 = __expf(sacc[jn][0] * SCALE);
                float e1 = __expf(sacc[jn][1] * SCALE);
                float e2 = __expf(sacc[jn][2] * SCALE);
                float e3 = __expf(sacc[jn][3] * SCALE);
                rs_lo += e0 + e1;
                rs_hi += e2 + e3;
                eh[jn][0] = packh2(e0, e1);
                eh[jn][1] = packh2(e2, e3);
            }
        } else {
#pragma unroll
            for (int jn = 0; jn < 8; jn++) {
                int j0 = k0 + jn * 8 + 2 * q;
                float e0 = (j0 < cnt)     ? __expf(sacc[jn][0] * SCALE) : 0.f;
                float e1 = (j0 + 1 < cnt) ? __expf(sacc[jn][1] * SCALE) : 0.f;
                float e2 = (j0 < cnt)     ? __expf(sacc[jn][2] * SCALE) : 0.f;
                float e3 = (j0 + 1 < cnt) ? __expf(sacc[jn][3] * SCALE) : 0.f;
                rs_lo += e0 + e1;
                rs_hi += e2 + e3;
                eh[jn][0] = packh2(e0, e1);
                eh[jn][1] = packh2(e2, e3);
            }
        }

        // ---- O += E V ----
#pragma unroll
        for (int js = 0; js < 4; js++) {
            uint32_t a0 = eh[2 * js][0], a1 = eh[2 * js][1];
            uint32_t a2 = eh[2 * js + 1][0], a3 = eh[2 * js + 1][1];
#pragma unroll
            for (int dnp = 0; dnp < 4; dnp++) {
                uint32_t b0, b1, b2, b3;
                ldsm_x4_t(b0, b1, b2, b3, vaddr0 + js * (16 * AQS * 2) + dnp * 32);
                mma16816(oacc[2 * dnp],     a0, a1, a2, a3, b0, b1);
                mma16816(oacc[2 * dnp + 1], a0, a1, a2, a3, b2, b3);
            }
        }
    }

    rs_lo += __shfl_xor_sync(0xffffffffu, rs_lo, 1);
    rs_lo += __shfl_xor_sync(0xffffffffu, rs_lo, 2);
    rs_hi += __shfl_xor_sync(0xffffffffu, rs_hi, 1);
    rs_hi += __shfl_xor_sync(0xffffffffu, rs_hi, 2);
    const float inv_lo = 1.f / rs_lo;
    const float inv_hi = 1.f / rs_hi;

    const int row0 = q0 + warp * 16 + g;
    __half* dst0 = g_x + (size_t)(b * SEQ + row0) * DIM + h * HDIM + 2 * q;
    __half* dst1 = g_x + (size_t)(b * SEQ + row0 + 8) * DIM + h * HDIM + 2 * q;
#pragma unroll
    for (int dn = 0; dn < 8; dn++) {
        uint32_t lo = packh2(oacc[dn][0] * inv_lo, oacc[dn][1] * inv_lo);
        uint32_t hi = packh2(oacc[dn][2] * inv_hi, oacc[dn][3] * inv_hi);
        *(uint32_t*)&dst0[dn * 8] = lo;
        *(uint32_t*)&dst1[dn * 8] = hi;
    }
}

// ---------------------------------------------------------------------------
// Kernel 3: FC projection, 128x128 tile / 64x64 warp tile (qkv shape),
// bias fused, float output.
// ---------------------------------------------------------------------------
__global__ __launch_bounds__(128) void fc_kernel(
    const float* __restrict__ bias, float* __restrict__ out)
{
    __shared__ __half As[128 * LDH];
    __shared__ __half Ws[128 * LDH];

    const int tid = threadIdx.x;
    const int warp = tid >> 5;
    const int lane = tid & 31;
    const int wy = warp >> 1;
    const int wx = warp & 1;
    const int m0 = blockIdx.y << 7;
    const int d0 = blockIdx.x << 7;

    HC acc[4][4];
#pragma unroll
    for (int i = 0; i < 4; i++)
#pragma unroll
        for (int j = 0; j < 4; j++) wmma::fill_fragment(acc[i][j], 0.f);

    const int ar = tid >> 2;
    const int ac8 = (tid & 3) << 3;

    uint4 pa[4], pw[4];
#pragma unroll
    for (int i = 0; i < 4; i++) {
        pa[i] = *(const uint4*)&g_x[(size_t)(m0 + ar + 32 * i) * DIM + ac8];
        pw[i] = *(const uint4*)&g_wf[(size_t)(d0 + ar + 32 * i) * DIM + ac8];
    }

    for (int c = 0; c < NCHUNK; c++) {
#pragma unroll
        for (int i = 0; i < 4; i++) {
            *(uint4*)&As[(ar + 32 * i) * LDH + ac8] = pa[i];
            *(uint4*)&Ws[(ar + 32 * i) * LDH + ac8] = pw[i];
        }
        __syncthreads();
        if (c + 1 < NCHUNK) {
            const int kc = (c + 1) * BK;
#pragma unroll
            for (int i = 0; i < 4; i++) {
                pa[i] = *(const uint4*)&g_x[(size_t)(m0 + ar + 32 * i) * DIM + kc + ac8];
                pw[i] = *(const uint4*)&g_wf[(size_t)(d0 + ar + 32 * i) * DIM + kc + ac8];
            }
        }
#pragma unroll
        for (int ks = 0; ks < 2; ks++) {
            HA am[4];
            HBc bn[4];
#pragma unroll
            for (int ms = 0; ms < 4; ms++)
                wmma::load_matrix_sync(am[ms], &As[(wy * 64 + ms * 16) * LDH + ks * 16], LDH);
#pragma unroll
            for (int ns = 0; ns < 4; ns++)
                wmma::load_matrix_sync(bn[ns], &Ws[(wx * 64 + ns * 16) * LDH + ks * 16], LDH);
#pragma unroll
            for (int ms = 0; ms < 4; ms++)
#pragma unroll
                for (int ns = 0; ns < 4; ns++)
                    wmma::mma_sync(acc[ms][ns], am[ms], bn[ns], acc[ms][ns]);
        }
        __syncthreads();
    }

    // Epilogue: per-warp smem staging, add bias, store float.
    float* Ep = (float*)As + warp * (16 * 20);
    const int row = lane >> 1, c0 = (lane & 1) << 3;
#pragma unroll
    for (int ms = 0; ms < 4; ms++)
#pragma unroll
        for (int ns = 0; ns < 4; ns++) {
            wmma::store_matrix_sync(Ep, acc[ms][ns], 20, wmma::mem_row_major);
            __syncwarp();
            const float* src = &Ep[row * 20 + c0];
            int d = d0 + wx * 64 + ns * 16 + c0;
            float4 v0 = *(const float4*)&src[0];
            float4 v1 = *(const float4*)&src[4];
            float4 b0 = *(const float4*)&bias[d];
            float4 b1 = *(const float4*)&bias[d + 4];
            v0.x += b0.x; v0.y += b0.y; v0.z += b0.z; v0.w += b0.w;
            v1.x += b1.x; v1.y += b1.y; v1.z += b1.z; v1.w += b1.w;
            float* op = &out[(size_t)(m0 + wy * 64 + ms * 16 + row) * DIM + d];
            *(float4*)&op[0] = v0;
            *(float4*)&op[4] = v1;
            __syncwarp();
        }
}

// ---------------------------------------------------------------------------
// Launch
// ---------------------------------------------------------------------------
extern "C" void kernel_launch(void* const* d_in, const int* in_sizes, int n_in,
                              void* d_out, int out_size)
{
    const float* inputs = (const float*)d_in[0];
    const int*   pmask  = (const int*)d_in[1];
    const float* w_qkv  = (const float*)d_in[2];
    const float* w_fc   = (const float*)d_in[3];
    const float* b_fc   = (const float*)d_in[4];
    float* out = (float*)d_out;

    compact_kernel<<<BATCH, 256>>>(pmask);
    convert_all_kernel<<<(N8_TOTAL + 255) / 256, 256>>>(inputs, w_qkv, w_fc);
    {
        dim3 grid(QKV_DIM / 128, M_TOTAL / 128); // (18, 32) = 576 CTAs
        qkv_kernel<<<grid, 128>>>();
    }
    {
        dim3 grid(SEQ / 128, BATCH * NHEAD);     // (16, 24)
        gather_kv_kernel<<<grid, 256>>>();
    }
    {
        dim3 grid(SEQ / 128, BATCH * NHEAD);     // (16, 24) = 384 CTAs
        attn_kernel<<<grid, 256>>>();
    }
    {
        dim3 grid(DIM / 128, M_TOTAL / 128);     // (6, 32) = 192 CTAs
        fc_kernel<<<grid, 128>>>(b_fc, out);
    }
}

// round 16
// speedup vs baseline: 1.0256x; 1.0256x over previous
#include <cuda_runtime.h>
#include <cuda_fp16.h>
#include <mma.h>
#include <math.h>
#include <stdint.h>

using namespace nvcuda;

// Problem constants
#define BATCH 2
#define SEQ 2048
#define DIM 768
#define NHEAD 12
#define HDIM 64
#define QKV_DIM (3 * DIM)     // 2304
#define M_TOTAL (BATCH * SEQ) // 4096
#define SCALE 0.125f          // 64^-0.5

// Scratch (device globals; no allocations allowed)
__device__ __half g_q[BATCH * NHEAD * SEQ * HDIM];
__device__ __half g_kc[BATCH * NHEAD * SEQ * HDIM];  // compacted+padded K
__device__ __half g_vc[BATCH * NHEAD * SEQ * HDIM];  // compacted+padded V
__device__ __half g_x[M_TOTAL * DIM];
__device__ __half g_a[M_TOTAL * DIM];     // fp16-rounded inputs
__device__ __half g_wq[QKV_DIM * DIM];    // fp16-rounded w_qkv
__device__ __half g_wf[DIM * DIM];        // fp16-rounded w_fc
__device__ int    g_dst[BATCH * SEQ];     // row n -> compacted slot (-1 masked)
__device__ int    g_cnt[BATCH];

typedef wmma::fragment<wmma::matrix_a, 16, 16, 16, __half, wmma::row_major> HA;
typedef wmma::fragment<wmma::matrix_b, 16, 16, 16, __half, wmma::col_major> HBc;
typedef wmma::fragment<wmma::accumulator, 16, 16, 16, float> HC;

__device__ __forceinline__ uint32_t smem_u32(const void* p) {
    uint32_t a;
    asm("{ .reg .u64 t; cvta.to.shared.u64 t, %1; cvt.u32.u64 %0, t; }" : "=r"(a) : "l"(p));
    return a;
}
__device__ __forceinline__ void ldsm_x4(uint32_t& r0, uint32_t& r1, uint32_t& r2,
                                        uint32_t& r3, uint32_t addr) {
    asm volatile("ldmatrix.sync.aligned.m8n8.x4.shared.b16 {%0,%1,%2,%3}, [%4];"
                 : "=r"(r0), "=r"(r1), "=r"(r2), "=r"(r3) : "r"(addr));
}
__device__ __forceinline__ void ldsm_x4_t(uint32_t& r0, uint32_t& r1, uint32_t& r2,
                                          uint32_t& r3, uint32_t addr) {
    asm volatile("ldmatrix.sync.aligned.m8n8.x4.trans.shared.b16 {%0,%1,%2,%3}, [%4];"
                 : "=r"(r0), "=r"(r1), "=r"(r2), "=r"(r3) : "r"(addr));
}
__device__ __forceinline__ void mma16816(float* c, uint32_t a0, uint32_t a1,
                                         uint32_t a2, uint32_t a3,
                                         uint32_t b0, uint32_t b1) {
    asm volatile(
        "mma.sync.aligned.m16n8k16.row.col.f32.f16.f16.f32 "
        "{%0,%1,%2,%3},{%4,%5,%6,%7},{%8,%9},{%0,%1,%2,%3};"
        : "+f"(c[0]), "+f"(c[1]), "+f"(c[2]), "+f"(c[3])
        : "r"(a0), "r"(a1), "r"(a2), "r"(a3), "r"(b0), "r"(b1));
}
__device__ __forceinline__ uint32_t packh2(float a, float b) {
    __half2 h = __floats2half2_rn(a, b);
    return *(uint32_t*)&h;
}

// ---------------------------------------------------------------------------
// Kernel -1: fused fp32 -> fp16 round-to-nearest for all three tensors.
// ---------------------------------------------------------------------------
#define N8_A (M_TOTAL * DIM / 8)
#define N8_WQ (QKV_DIM * DIM / 8)
#define N8_WF (DIM * DIM / 8)
#define N8_TOTAL (N8_A + N8_WQ + N8_WF)

__global__ void convert_all_kernel(const float* __restrict__ a,
                                   const float* __restrict__ wq,
                                   const float* __restrict__ wf)
{
    int i = blockIdx.x * blockDim.x + threadIdx.x;
    if (i >= N8_TOTAL) return;
    const float* src;
    __half* dst;
    int j;
    if (i < N8_A) {
        src = a; dst = g_a; j = i;
    } else if (i < N8_A + N8_WQ) {
        src = wq; dst = g_wq; j = i - N8_A;
    } else {
        src = wf; dst = g_wf; j = i - N8_A - N8_WQ;
    }
    float4 x = *(const float4*)&src[j * 8];
    float4 y = *(const float4*)&src[j * 8 + 4];
    __half2 h0 = __floats2half2_rn(x.x, x.y);
    __half2 h1 = __floats2half2_rn(x.z, x.w);
    __half2 h2 = __floats2half2_rn(y.x, y.y);
    __half2 h3 = __floats2half2_rn(y.z, y.w);
    uint4 u;
    u.x = *(uint32_t*)&h0; u.y = *(uint32_t*)&h1;
    u.z = *(uint32_t*)&h2; u.w = *(uint32_t*)&h3;
    *(uint4*)&dst[j * 8] = u;
}

// ---------------------------------------------------------------------------
// Kernel 0: per-batch compaction map. g_dst[b][n] = compacted slot of row n
// (-1 if masked). When ALL rows are masked (cnt==0), identity map so the
// uniform-softmax fallback can read g_vc directly.
// ---------------------------------------------------------------------------
__global__ void compact_kernel(const int* __restrict__ mask)
{
    __shared__ int cnts[256];
    const int b = blockIdx.x;
    const int t = threadIdx.x;
    const int PER = SEQ / 256; // 8

    int m[PER];
    int local = 0;
#pragma unroll
    for (int i = 0; i < PER; i++) {
        m[i] = mask[b * SEQ + t * PER + i];
        local += (m[i] <= 0);
    }
    cnts[t] = local;
    __syncthreads();
    for (int off = 1; off < 256; off <<= 1) {
        int v = (t >= off) ? cnts[t - off] : 0;
        __syncthreads();
        cnts[t] += v;
        __syncthreads();
    }
    const int total = cnts[255];
    int w = cnts[t] - local;
#pragma unroll
    for (int i = 0; i < PER; i++) {
        int pos = t * PER + i;
        int d;
        if (total == 0) d = pos;                    // identity fallback
        else if (m[i] <= 0) d = w++;
        else d = -1;
        g_dst[b * SEQ + pos] = d;
    }
    if (t == 255) g_cnt[b] = total;
}

// ---------------------------------------------------------------------------
// Kernel 0b: zero the pad rows [cnt, cnt64) of g_kc/g_vc per head.
// ---------------------------------------------------------------------------
__global__ void pad_kv_kernel()
{
    const int bh = blockIdx.x;
    const int b = bh / NHEAD;
    const int cnt = g_cnt[b];
    const int cnt64 = (cnt + 63) & ~63;
    const int npad = cnt64 - cnt;           // 0..63
    if (npad == 0) return;
    __half* kc = g_kc + (size_t)bh * SEQ * HDIM;
    __half* vc = g_vc + (size_t)bh * SEQ * HDIM;
    const uint4 z = make_uint4(0, 0, 0, 0);
    for (int idx = threadIdx.x; idx < npad * 8; idx += 256) {
        int r = cnt + (idx >> 3);
        int c8 = (idx & 7) << 3;
        *(uint4*)&kc[(size_t)r * HDIM + c8] = z;
        *(uint4*)&vc[(size_t)r * HDIM + c8] = z;
    }
}

// ---------------------------------------------------------------------------
// fp16 GEMM config.
// ---------------------------------------------------------------------------
#define BK 32
#define LDH 40
#define NCHUNK (DIM / BK)  // 24

// ---------------------------------------------------------------------------
// Kernel 1: QKV projection. Q written at row n; K/V rows scattered directly
// into compacted slots of g_kc/g_vc via g_dst (masked rows dropped).
// ---------------------------------------------------------------------------
__global__ __launch_bounds__(128) void qkv_kernel()
{
    __shared__ __half As[128 * LDH];
    __shared__ __half Ws[128 * LDH];

    const int tid = threadIdx.x;
    const int warp = tid >> 5;
    const int lane = tid & 31;
    const int wy = warp >> 1;
    const int wx = warp & 1;
    const int m0 = blockIdx.y << 7;
    const int d0 = blockIdx.x << 7;

    HC acc[4][4];
#pragma unroll
    for (int i = 0; i < 4; i++)
#pragma unroll
        for (int j = 0; j < 4; j++) wmma::fill_fragment(acc[i][j], 0.f);

    const int ar = tid >> 2;
    const int ac8 = (tid & 3) << 3;

    uint4 pa[4], pw[4];
#pragma unroll
    for (int i = 0; i < 4; i++) {
        pa[i] = *(const uint4*)&g_a[(size_t)(m0 + ar + 32 * i) * DIM + ac8];
        pw[i] = *(const uint4*)&g_wq[(size_t)(d0 + ar + 32 * i) * DIM + ac8];
    }

    for (int c = 0; c < NCHUNK; c++) {
#pragma unroll
        for (int i = 0; i < 4; i++) {
            *(uint4*)&As[(ar + 32 * i) * LDH + ac8] = pa[i];
            *(uint4*)&Ws[(ar + 32 * i) * LDH + ac8] = pw[i];
        }
        __syncthreads();
        if (c + 1 < NCHUNK) {
            const int kc = (c + 1) * BK;
#pragma unroll
            for (int i = 0; i < 4; i++) {
                pa[i] = *(const uint4*)&g_a[(size_t)(m0 + ar + 32 * i) * DIM + kc + ac8];
                pw[i] = *(const uint4*)&g_wq[(size_t)(d0 + ar + 32 * i) * DIM + kc + ac8];
            }
        }
#pragma unroll
        for (int ks = 0; ks < 2; ks++) {
            HA am[4];
            HBc bn[4];
#pragma unroll
            for (int ms = 0; ms < 4; ms++)
                wmma::load_matrix_sync(am[ms], &As[(wy * 64 + ms * 16) * LDH + ks * 16], LDH);
#pragma unroll
            for (int ns = 0; ns < 4; ns++)
                wmma::load_matrix_sync(bn[ns], &Ws[(wx * 64 + ns * 16) * LDH + ks * 16], LDH);
#pragma unroll
            for (int ms = 0; ms < 4; ms++)
#pragma unroll
                for (int ns = 0; ns < 4; ns++)
                    wmma::mma_sync(acc[ms][ns], am[ms], bn[ns], acc[ms][ns]);
        }
        __syncthreads();
    }

    float* Ep = (float*)As + warp * (16 * 20);
    const int bIdx = m0 >> 11;
    const int n0 = (m0 & 2047) + wy * 64;
    const int dg = d0 + wx * 64;
    const int which = dg / DIM;            // 0=Q, 1=K, 2=V (block-uniform)
    const int dbase = dg % DIM;
    __half* dstb = (which == 0) ? g_q : (which == 1) ? g_kc : g_vc;
    const size_t headbase0 = ((size_t)bIdx * NHEAD) * SEQ;
    const int* dmap = g_dst + bIdx * SEQ;
    const int row = lane >> 1, c0 = (lane & 1) << 3;

#pragma unroll
    for (int ms = 0; ms < 4; ms++) {
        const int n = n0 + ms * 16 + row;
        const int dr = (which == 0) ? n : dmap[n];
#pragma unroll
        for (int ns = 0; ns < 4; ns++) {
            wmma::store_matrix_sync(Ep, acc[ms][ns], 20, wmma::mem_row_major);
            __syncwarp();
            if (dr >= 0) {
                const float* src = &Ep[row * 20 + c0];
                __half tmp[8];
#pragma unroll
                for (int j = 0; j < 8; j++) tmp[j] = __float2half_rn(src[j]);
                int dl = dbase + ns * 16;
                int h = dl >> 6;
                int hd = (dl & 63) + c0;
                size_t off = (headbase0 + (size_t)h * SEQ + dr) * HDIM + hd;
                *(uint4*)&dstb[off] = *(uint4*)tmp;
            }
            __syncwarp();
        }
    }
}

// ---------------------------------------------------------------------------
// Kernel 2: flash attention, raw mma.m16n8k16, in-register softmax, over
// compacted contiguous K/V. Sequential loads; mask only on the final tile.
// ---------------------------------------------------------------------------
#define AQS 72  // smem stride (halves) for Q/K/V tiles

__global__ __launch_bounds__(256, 2) void attn_kernel()
{
    __shared__ __half Qs[128 * AQS];   // 18432 B
    __shared__ __half Ks[64 * AQS];    //  9216 B
    __shared__ __half Vs[64 * AQS];    //  9216 B
    __shared__ float meanv[64];

    const int tid = threadIdx.x;
    const int warp = tid >> 5;
    const int lane = tid & 31;
    const int g = lane >> 2;
    const int q = lane & 3;
    const int bh = blockIdx.y;
    const int b = bh / NHEAD, h = bh % NHEAD;
    const int q0 = blockIdx.x * 128;
    const __half* qb = g_q + (size_t)bh * SEQ * HDIM;
    const __half* kcb = g_kc + (size_t)bh * SEQ * HDIM;
    const __half* vcb = g_vc + (size_t)bh * SEQ * HDIM;
    const int cnt = g_cnt[b];

    if (cnt == 0) {
        // All keys masked: softmax uniform -> output = mean of V rows.
        // (g_vc holds the identity layout in this case.)
        if (tid < 64) {
            float acc = 0.f;
            for (int k = 0; k < SEQ; k++) acc += __half2float(vcb[(size_t)k * HDIM + tid]);
            meanv[tid] = acc / (float)SEQ;
        }
        __syncthreads();
        int row = tid >> 1, half32 = (tid & 1) * 32;
        __half* dst = g_x + (size_t)(b * SEQ + q0 + row) * DIM + h * HDIM + half32;
#pragma unroll
        for (int c = 0; c < 32; c++) dst[c] = __float2half_rn(meanv[half32 + c]);
        return;
    }

    // Load Q tile (128 x 64 halves) into Qs
#pragma unroll
    for (int i = 0; i < 4; i++) {
        int idx = tid + 256 * i;
        int r = idx >> 3, c8 = (idx & 7) << 3;
        *(uint4*)&Qs[r * AQS + c8] = *(const uint4*)&qb[(size_t)(q0 + r) * HDIM + c8];
    }
    __syncthreads();

    const int lm = lane >> 3, lr8 = lane & 7;

    // Q A-frags preloaded, reused all tiles.
    uint32_t aq[4][4];
    {
        uint32_t qaddr = smem_u32(&Qs[(warp * 16 + (lm & 1) * 8 + lr8) * AQS + (lm >> 1) * 8]);
#pragma unroll
        for (int ks = 0; ks < 4; ks++)
            ldsm_x4(aq[ks][0], aq[ks][1], aq[ks][2], aq[ks][3], qaddr + ks * 32);
    }

    const uint32_t kaddr0 = smem_u32(&Ks[((lm >> 1) * 8 + lr8) * AQS + (lm & 1) * 8]);
    const uint32_t vaddr0 = smem_u32(&Vs[((lm & 1) * 8 + lr8) * AQS + (lm >> 1) * 8]);

    float oacc[8][4];
#pragma unroll
    for (int dn = 0; dn < 8; dn++)
#pragma unroll
        for (int e = 0; e < 4; e++) oacc[dn][e] = 0.f;
    float rs_lo = 0.f, rs_hi = 0.f;

    const int ntiles = (cnt + 63) >> 6;

    const int lrr = tid >> 3;            // row 0..31 (+32 for i=1)
    const int lc8 = (tid & 7) << 3;      // col

    // Prologue: tile 0 (sequential, unguarded - pad is zeroed)
    uint4 kreg[2], vreg[2];
#pragma unroll
    for (int i = 0; i < 2; i++) {
        kreg[i] = *(const uint4*)&kcb[(size_t)(lrr + 32 * i) * HDIM + lc8];
        vreg[i] = *(const uint4*)&vcb[(size_t)(lrr + 32 * i) * HDIM + lc8];
    }

    for (int tile = 0; tile < ntiles; tile++) {
        const int k0 = tile << 6;
        __syncthreads(); // prev-tile ldmatrix reads of Ks/Vs done

#pragma unroll
        for (int i = 0; i < 2; i++) {
            *(uint4*)&Ks[(lrr + 32 * i) * AQS + lc8] = kreg[i];
            *(uint4*)&Vs[(lrr + 32 * i) * AQS + lc8] = vreg[i];
        }
        __syncthreads(); // K/V visible

        // Prefetch next tile (sequential, unguarded)
        if (tile + 1 < ntiles) {
            const int kn = k0 + 64;
#pragma unroll
            for (int i = 0; i < 2; i++) {
                kreg[i] = *(const uint4*)&kcb[(size_t)(kn + lrr + 32 * i) * HDIM + lc8];
                vreg[i] = *(const uint4*)&vcb[(size_t)(kn + lrr + 32 * i) * HDIM + lc8];
            }
        }

        // ---- S = Q K^T (16 x 64 per warp) in registers ----
        float sacc[8][4];
#pragma unroll
        for (int jn = 0; jn < 8; jn++)
#pragma unroll
            for (int e = 0; e < 4; e++) sacc[jn][e] = 0.f;

#pragma unroll
        for (int ks = 0; ks < 4; ks++) {
#pragma unroll
            for (int jnp = 0; jnp < 4; jnp++) {
                uint32_t b0, b1, b2, b3;
                ldsm_x4(b0, b1, b2, b3, kaddr0 + jnp * (16 * AQS * 2) + ks * 32);
                mma16816(sacc[2 * jnp],     aq[ks][0], aq[ks][1], aq[ks][2], aq[ks][3], b0, b1);
                mma16816(sacc[2 * jnp + 1], aq[ks][0], aq[ks][1], aq[ks][2], aq[ks][3], b2, b3);
            }
        }

        // ---- exp in-register; mask only on the final partial tile ----
        uint32_t eh[8][2];
        if (k0 + 64 <= cnt) {
#pragma unroll
            for (int jn = 0; jn < 8; jn++) {
                float e0 = __expf(sacc[jn][0] * SCALE);
                float e1 = __expf(sacc[jn][1] * SCALE);
                float e2 = __expf(sacc[jn][2] * SCALE);
                float e3 = __expf(sacc[jn][3] * SCALE);
                rs_lo += e0 + e1;
                rs_hi += e2 + e3;
                eh[jn][0] = packh2(e0, e1);
                eh[jn][1] = packh2(e2, e3);
            }
        } else {
#pragma unroll
            for (int jn = 0; jn < 8; jn++) {
                int j0 = k0 + jn * 8 + 2 * q;
                float e0 = (j0 < cnt)     ? __expf(sacc[jn][0] * SCALE) : 0.f;
                float e1 = (j0 + 1 < cnt) ? __expf(sacc[jn][1] * SCALE) : 0.f;
                float e2 = (j0 < cnt)     ? __expf(sacc[jn][2] * SCALE) : 0.f;
                float e3 = (j0 + 1 < cnt) ? __expf(sacc[jn][3] * SCALE) : 0.f;
                rs_lo += e0 + e1;
                rs_hi += e2 + e3;
                eh[jn][0] = packh2(e0, e1);
                eh[jn][1] = packh2(e2, e3);
            }
        }

        // ---- O += E V ----
#pragma unroll
        for (int js = 0; js < 4; js++) {
            uint32_t a0 = eh[2 * js][0], a1 = eh[2 * js][1];
            uint32_t a2 = eh[2 * js + 1][0], a3 = eh[2 * js + 1][1];
#pragma unroll
            for (int dnp = 0; dnp < 4; dnp++) {
                uint32_t b0, b1, b2, b3;
                ldsm_x4_t(b0, b1, b2, b3, vaddr0 + js * (16 * AQS * 2) + dnp * 32);
                mma16816(oacc[2 * dnp],     a0, a1, a2, a3, b0, b1);
                mma16816(oacc[2 * dnp + 1], a0, a1, a2, a3, b2, b3);
            }
        }
    }

    rs_lo += __shfl_xor_sync(0xffffffffu, rs_lo, 1);
    rs_lo += __shfl_xor_sync(0xffffffffu, rs_lo, 2);
    rs_hi += __shfl_xor_sync(0xffffffffu, rs_hi, 1);
    rs_hi += __shfl_xor_sync(0xffffffffu, rs_hi, 2);
    const float inv_lo = 1.f / rs_lo;
    const float inv_hi = 1.f / rs_hi;

    const int row0 = q0 + warp * 16 + g;
    __half* dst0 = g_x + (size_t)(b * SEQ + row0) * DIM + h * HDIM + 2 * q;
    __half* dst1 = g_x + (size_t)(b * SEQ + row0 + 8) * DIM + h * HDIM + 2 * q;
#pragma unroll
    for (int dn = 0; dn < 8; dn++) {
        uint32_t lo = packh2(oacc[dn][0] * inv_lo, oacc[dn][1] * inv_lo);
        uint32_t hi = packh2(oacc[dn][2] * inv_hi, oacc[dn][3] * inv_hi);
        *(uint32_t*)&dst0[dn * 8] = lo;
        *(uint32_t*)&dst1[dn * 8] = hi;
    }
}

// ---------------------------------------------------------------------------
// Kernel 3: FC projection, 128x128 tile / 64x64 warp tile, bias fused.
// ---------------------------------------------------------------------------
__global__ __launch_bounds__(128) void fc_kernel(
    const float* __restrict__ bias, float* __restrict__ out)
{
    __shared__ __half As[128 * LDH];
    __shared__ __half Ws[128 * LDH];

    const int tid = threadIdx.x;
    const int warp = tid >> 5;
    const int lane = tid & 31;
    const int wy = warp >> 1;
    const int wx = warp & 1;
    const int m0 = blockIdx.y << 7;
    const int d0 = blockIdx.x << 7;

    HC acc[4][4];
#pragma unroll
    for (int i = 0; i < 4; i++)
#pragma unroll
        for (int j = 0; j < 4; j++) wmma::fill_fragment(acc[i][j], 0.f);

    const int ar = tid >> 2;
    const int ac8 = (tid & 3) << 3;

    uint4 pa[4], pw[4];
#pragma unroll
    for (int i = 0; i < 4; i++) {
        pa[i] = *(const uint4*)&g_x[(size_t)(m0 + ar + 32 * i) * DIM + ac8];
        pw[i] = *(const uint4*)&g_wf[(size_t)(d0 + ar + 32 * i) * DIM + ac8];
    }

    for (int c = 0; c < NCHUNK; c++) {
#pragma unroll
        for (int i = 0; i < 4; i++) {
            *(uint4*)&As[(ar + 32 * i) * LDH + ac8] = pa[i];
            *(uint4*)&Ws[(ar + 32 * i) * LDH + ac8] = pw[i];
        }
        __syncthreads();
        if (c + 1 < NCHUNK) {
            const int kc = (c + 1) * BK;
#pragma unroll
            for (int i = 0; i < 4; i++) {
                pa[i] = *(const uint4*)&g_x[(size_t)(m0 + ar + 32 * i) * DIM + kc + ac8];
                pw[i] = *(const uint4*)&g_wf[(size_t)(d0 + ar + 32 * i) * DIM + kc + ac8];
            }
        }
#pragma unroll
        for (int ks = 0; ks < 2; ks++) {
            HA am[4];
            HBc bn[4];
#pragma unroll
            for (int ms = 0; ms < 4; ms++)
                wmma::load_matrix_sync(am[ms], &As[(wy * 64 + ms * 16) * LDH + ks * 16], LDH);
#pragma unroll
            for (int ns = 0; ns < 4; ns++)
                wmma::load_matrix_sync(bn[ns], &Ws[(wx * 64 + ns * 16) * LDH + ks * 16], LDH);
#pragma unroll
            for (int ms = 0; ms < 4; ms++)
#pragma unroll
                for (int ns = 0; ns < 4; ns++)
                    wmma::mma_sync(acc[ms][ns], am[ms], bn[ns], acc[ms][ns]);
        }
        __syncthreads();
    }

    float* Ep = (float*)As + warp * (16 * 20);
    const int row = lane >> 1, c0 = (lane & 1) << 3;
#pragma unroll
    for (int ms = 0; ms < 4; ms++)
#pragma unroll
        for (int ns = 0; ns < 4; ns++) {
            wmma::store_matrix_sync(Ep, acc[ms][ns], 20, wmma::mem_row_major);
            __syncwarp();
            const float* src = &Ep[row * 20 + c0];
            int d = d0 + wx * 64 + ns * 16 + c0;
            float4 v0 = *(const float4*)&src[0];
            float4 v1 = *(const float4*)&src[4];
            float4 b0 = *(const float4*)&bias[d];
            float4 b1 = *(const float4*)&bias[d + 4];
            v0.x += b0.x; v0.y += b0.y; v0.z += b0.z; v0.w += b0.w;
            v1.x += b1.x; v1.y += b1.y; v1.z += b1.z; v1.w += b1.w;
            float* op = &out[(size_t)(m0 + wy * 64 + ms * 16 + row) * DIM + d];
            *(float4*)&op[0] = v0;
            *(float4*)&op[4] = v1;
            __syncwarp();
        }
}

// ---------------------------------------------------------------------------
// Launch
// ---------------------------------------------------------------------------
extern "C" void kernel_launch(void* const* d_in, const int* in_sizes, int n_in,
                              void* d_out, int out_size)
{
    const float* inputs = (const float*)d_in[0];
    const int*   pmask  = (const int*)d_in[1];
    const float* w_qkv  = (const float*)d_in[2];
    const float* w_fc   = (const float*)d_in[3];
    const float* b_fc   = (const float*)d_in[4];
    float* out = (float*)d_out;

    compact_kernel<<<BATCH, 256>>>(pmask);
    convert_all_kernel<<<(N8_TOTAL + 255) / 256, 256>>>(inputs, w_qkv, w_fc);
    pad_kv_kernel<<<BATCH * NHEAD, 256>>>();
    {
        dim3 grid(QKV_DIM / 128, M_TOTAL / 128); // (18, 32) = 576 CTAs
        qkv_kernel<<<grid, 128>>>();
    }
    {
        dim3 grid(SEQ / 128, BATCH * NHEAD);     // (16, 24) = 384 CTAs
        attn_kernel<<<grid, 256>>>();
    }
    {
        dim3 grid(DIM / 128, M_TOTAL / 128);     // (6, 32) = 192 CTAs
        fc_kernel<<<grid, 128>>>(b_fc, out);
    }
}